// round 15
// baseline (speedup 1.0000x reference)
#include <cuda_runtime.h>
#include <cuda_bf16.h>
#include <math.h>
#include <stdint.h>

#define AR 8192
#define ED 1024
#define MD 1024

// ---------------- device scratch ----------------
__device__ __nv_bfloat16 g_a1[(size_t)AR * ED];
__device__ __nv_bfloat16 g_a2[(size_t)AR * ED];
__device__ __nv_bfloat16 g_wb1[(size_t)MD * ED];
__device__ __nv_bfloat16 g_wb2[(size_t)MD * ED];
__device__ __nv_bfloat16 g_p1[(size_t)AR * MD];
__device__ __nv_bfloat16 g_p2[(size_t)AR * MD];
__device__ float g_s1[MD];
__device__ float g_s2[MD];
__device__ float g_bias1[MD];
__device__ float g_bias2[MD];
__device__ float g_logits[2 * AR];
__device__ float g_max[2];
__device__ float g_z[2];

__device__ __forceinline__ float elu1(float x) { return x > 0.0f ? x : expm1f(x); }

__device__ __forceinline__ void atomicMaxF(float* a, float v) {
    if (v >= 0.0f) atomicMax((int*)a, __float_as_int(v));
    else atomicMin((unsigned int*)a, __float_as_uint(v));
}

__device__ __forceinline__ uint32_t smem_u32(const void* p) {
    uint32_t a;
    asm("{ .reg .u64 t; cvta.to.shared.u64 t, %1; cvt.u32.u64 %0, t; }" : "=r"(a) : "l"(p));
    return a;
}
#define CP_ASYNC16(dst, src) \
    asm volatile("cp.async.cg.shared.global [%0], [%1], 16;" :: "r"(dst), "l"(src))
#define CP_COMMIT() asm volatile("cp.async.commit_group;" ::: "memory")
#define CP_WAIT1()  asm volatile("cp.async.wait_group 1;" ::: "memory")
#define LDMATRIX_X4(r0, r1, r2, r3, addr) \
    asm volatile("ldmatrix.sync.aligned.m8n8.x4.shared.b16 {%0,%1,%2,%3}, [%4];" \
        : "=r"(r0), "=r"(r1), "=r"(r2), "=r"(r3) : "r"(addr))
#define MMA16816(c0, c1, c2, c3, a0, a1, a2, a3, b0, b1) \
    asm volatile("mma.sync.aligned.m16n8k16.row.col.f32.bf16.bf16.f32 " \
        "{%0,%1,%2,%3}, {%4,%5,%6,%7}, {%8,%9}, {%0,%1,%2,%3};" \
        : "+f"(c0), "+f"(c1), "+f"(c2), "+f"(c3) \
        : "r"(a0), "r"(a1), "r"(a2), "r"(a3), "r"(b0), "r"(b1))

// ---------------- merged conv: all 4 tensors f32 -> bf16, 16 f32/thread ----
#define SEQ_F16 (AR * ED / 16)    // 524288
#define W_F16   (MD * ED / 16)    // 65536
#define TOT_F16 (2 * SEQ_F16 + 2 * W_F16)

__global__ void conv_all_kernel(const float* __restrict__ seq1, const float* __restrict__ seq2,
                                const float* __restrict__ W1, const float* __restrict__ W2) {
    int i = blockIdx.x * blockDim.x + threadIdx.x;
    if (i >= TOT_F16) return;
    const float* src;
    __nv_bfloat16* dst;
    int off;
    if (i < SEQ_F16)                 { src = seq1; dst = g_a1;  off = i; }
    else if (i < 2 * SEQ_F16)        { src = seq2; dst = g_a2;  off = i - SEQ_F16; }
    else if (i < 2 * SEQ_F16 + W_F16){ src = W1;   dst = g_wb1; off = i - 2 * SEQ_F16; }
    else                             { src = W2;   dst = g_wb2; off = i - 2 * SEQ_F16 - W_F16; }
    const float4* s4 = (const float4*)src + 4 * (size_t)off;
    float4 v0 = s4[0], v1 = s4[1], v2 = s4[2], v3 = s4[3];
    uint4 o0, o1;
    asm("cvt.rn.bf16x2.f32 %0, %1, %2;" : "=r"(o0.x) : "f"(v0.y), "f"(v0.x));
    asm("cvt.rn.bf16x2.f32 %0, %1, %2;" : "=r"(o0.y) : "f"(v0.w), "f"(v0.z));
    asm("cvt.rn.bf16x2.f32 %0, %1, %2;" : "=r"(o0.z) : "f"(v1.y), "f"(v1.x));
    asm("cvt.rn.bf16x2.f32 %0, %1, %2;" : "=r"(o0.w) : "f"(v1.w), "f"(v1.z));
    asm("cvt.rn.bf16x2.f32 %0, %1, %2;" : "=r"(o1.x) : "f"(v2.y), "f"(v2.x));
    asm("cvt.rn.bf16x2.f32 %0, %1, %2;" : "=r"(o1.y) : "f"(v2.w), "f"(v2.z));
    asm("cvt.rn.bf16x2.f32 %0, %1, %2;" : "=r"(o1.z) : "f"(v3.y), "f"(v3.x));
    asm("cvt.rn.bf16x2.f32 %0, %1, %2;" : "=r"(o1.w) : "f"(v3.w), "f"(v3.z));
    ((uint4*)dst)[2 * (size_t)off] = o0;
    ((uint4*)dst)[2 * (size_t)off + 1] = o1;
}

// ---------------- zero + ctx GEMV fused ----------------
__global__ void zeroctx_kernel(const float* __restrict__ ctx,
                               const float* __restrict__ Wc1, const float* __restrict__ Wc2,
                               const float* __restrict__ b1, const float* __restrict__ b2,
                               float* __restrict__ out) {
    int gid = blockIdx.x * blockDim.x + threadIdx.x;
    if (gid < MD) { g_s1[gid] = 0.0f; g_s2[gid] = 0.0f; }
    if (gid < 2 * ED) out[gid] = 0.0f;
    if (gid < 2) { g_max[gid] = -INFINITY; g_z[gid] = 0.0f; }

    int g = gid >> 5;
    int lane = gid & 31;
    int mat = g >> 10, row = g & 1023;
    const float* W = mat ? Wc2 : Wc1;
    const float* b = mat ? b2 : b1;
    float* o = mat ? g_bias2 : g_bias1;
    float acc = 0.0f;
    const float* wr = W + (size_t)row * ED;
    for (int k = lane; k < ED; k += 32) acc += wr[k] * ctx[k];
    #pragma unroll
    for (int off = 16; off > 0; off >>= 1) acc += __shfl_down_sync(0xffffffffu, acc, off);
    if (lane == 0) o[row] = b[row] + acc;
}

// ---------------- bf16 mma.sync GEMM: 64x128 tiles, 3 CTAs/SM -------------
// CTA 64(M) x 128(N), BK=64, 2-stage. 8 warps 2(M)x4(N) -> warp 32x32.
// 2048 CTAs over 444 slots = 4.61 -> 5 waves (8.4% tail vs 15.6% at 128x128).
#define TM 64
#define TN 128
#define BK 64
#define NCHUNK (ED / BK)                     // 16
#define STAGE_BYTES ((TM + TN) * 128)        // 24KB

__global__ void __launch_bounds__(256, 3)
gemm_mma_kernel(const __nv_bfloat16* __restrict__ A1, const __nv_bfloat16* __restrict__ B1,
                const float* __restrict__ bias1v, __nv_bfloat16* __restrict__ P1,
                float* __restrict__ S1,
                const __nv_bfloat16* __restrict__ A2, const __nv_bfloat16* __restrict__ B2,
                const float* __restrict__ bias2v, __nv_bfloat16* __restrict__ P2,
                float* __restrict__ S2) {
    extern __shared__ __align__(128) char dyn[];
    __shared__ float bias_s[TN];

    const int z = blockIdx.z;
    const __nv_bfloat16* A = z ? A2 : A1;
    const __nv_bfloat16* W = z ? B2 : B1;
    const float* bias = z ? bias2v : bias1v;
    __nv_bfloat16* P = z ? P2 : P1;
    float* S = z ? S2 : S1;

    const int tid = threadIdx.x;
    const int wid = tid >> 5, lane = tid & 31;
    const int rowBlock = blockIdx.y * TM;
    const int colBlock = blockIdx.x * TN;

    uint32_t sbase = (smem_u32(dyn) + 127u) & ~127u;

    if (tid < TN) bias_s[tid] = bias[colBlock + tid];

    const int m0 = (wid & 1) * 32;
    const int n0 = (wid >> 1) * 32;

    float acc[2][4][4];
    #pragma unroll
    for (int i = 0; i < 2; i++)
        #pragma unroll
        for (int j = 0; j < 4; j++)
            #pragma unroll
            for (int q = 0; q < 4; q++) acc[i][j][q] = 0.0f;

    // loader: A rows 0..63 (512 segs) + W rows 64..191 (1024 segs) = 6/thread
    auto load_chunk = [&](int chunk, int stage) {
        const int k0 = chunk * BK;
        uint32_t base = sbase + stage * STAGE_BYTES;
        #pragma unroll
        for (int l = 0; l < 6; l++) {
            int i = tid + l * 256;             // 0..1535
            const __nv_bfloat16* src;
            int pr;                            // physical smem row
            int c;
            if (i < 512) {
                pr = i >> 3; c = i & 7;
                src = A + (size_t)(rowBlock + pr) * ED + k0 + c * 8;
            } else {
                int j = i - 512;
                int r = j >> 3; c = j & 7;
                pr = TM + r;
                src = W + (size_t)(colBlock + r) * ED + k0 + c * 8;
            }
            uint32_t dst = base + (uint32_t)(pr * 128) + (uint32_t)((c ^ (pr & 7)) << 4);
            CP_ASYNC16(dst, src);
        }
        CP_COMMIT();
    };

    load_chunk(0, 0);
    load_chunk(1, 1);

    const int lr = lane & 7, sub = lane >> 3;
    int arow[2], brow[2];
    uint32_t aswz[2], bswz[2];
    #pragma unroll
    for (int mi = 0; mi < 2; mi++) {
        int r = m0 + mi * 16 + ((sub & 1) << 3) + lr;
        arow[mi] = r * 128; aswz[mi] = (uint32_t)(r & 7);
    }
    const uint32_t achunkbit = (uint32_t)(sub >> 1);
    #pragma unroll
    for (int p = 0; p < 2; p++) {
        int r = TM + n0 + p * 16 + ((sub >> 1) << 3) + lr;
        brow[p] = r * 128; bswz[p] = (uint32_t)(r & 7);
    }
    const uint32_t bchunkbit = (uint32_t)(sub & 1);

    for (int ch = 0; ch < NCHUNK; ch++) {
        const int s = ch & 1;
        CP_WAIT1();
        __syncthreads();
        uint32_t base = sbase + s * STAGE_BYTES;

        #pragma unroll
        for (int ks = 0; ks < 4; ks++) {
            uint32_t a[2][4], b[8];
            #pragma unroll
            for (int mi = 0; mi < 2; mi++) {
                uint32_t addr = base + (uint32_t)arow[mi] +
                                ((((uint32_t)(ks << 1) | achunkbit) ^ aswz[mi]) << 4);
                LDMATRIX_X4(a[mi][0], a[mi][1], a[mi][2], a[mi][3], addr);
            }
            #pragma unroll
            for (int p = 0; p < 2; p++) {
                uint32_t addr = base + (uint32_t)brow[p] +
                                ((((uint32_t)(ks << 1) | bchunkbit) ^ bswz[p]) << 4);
                LDMATRIX_X4(b[p * 4 + 0], b[p * 4 + 1], b[p * 4 + 2], b[p * 4 + 3], addr);
            }
            #pragma unroll
            for (int mi = 0; mi < 2; mi++)
                #pragma unroll
                for (int nt = 0; nt < 4; nt++)
                    MMA16816(acc[mi][nt][0], acc[mi][nt][1], acc[mi][nt][2], acc[mi][nt][3],
                             a[mi][0], a[mi][1], a[mi][2], a[mi][3],
                             b[nt * 2], b[nt * 2 + 1]);
        }
        __syncthreads();
        if (ch < NCHUNK - 2) load_chunk(ch + 2, s);
        else CP_COMMIT();
    }

    // epilogue: bias + elu -> bf16 stores, fused column sums
    const int qrow = lane >> 2;
    const int qcol = (lane & 3) * 2;
    float csum[4][2];
    #pragma unroll
    for (int nt = 0; nt < 4; nt++) { csum[nt][0] = 0.0f; csum[nt][1] = 0.0f; }

    #pragma unroll
    for (int mi = 0; mi < 2; mi++) {
        #pragma unroll
        for (int nt = 0; nt < 4; nt++) {
            int col = n0 + nt * 8 + qcol;
            float bv0 = bias_s[col], bv1 = bias_s[col + 1];
            int r0 = rowBlock + m0 + mi * 16 + qrow;
            float x0 = elu1(acc[mi][nt][0] + bv0);
            float x1 = elu1(acc[mi][nt][1] + bv1);
            float x2 = elu1(acc[mi][nt][2] + bv0);
            float x3 = elu1(acc[mi][nt][3] + bv1);
            csum[nt][0] += x0 + x2;
            csum[nt][1] += x1 + x3;
            uint32_t p01, p23;
            asm("cvt.rn.bf16x2.f32 %0, %1, %2;" : "=r"(p01) : "f"(x1), "f"(x0));
            asm("cvt.rn.bf16x2.f32 %0, %1, %2;" : "=r"(p23) : "f"(x3), "f"(x2));
            *(uint32_t*)(P + (size_t)r0 * MD + colBlock + col) = p01;
            *(uint32_t*)(P + (size_t)(r0 + 8) * MD + colBlock + col) = p23;
        }
    }
    #pragma unroll
    for (int nt = 0; nt < 4; nt++) {
        #pragma unroll
        for (int q = 0; q < 2; q++) {
            float v = csum[nt][q];
            v += __shfl_xor_sync(0xffffffffu, v, 4);
            v += __shfl_xor_sync(0xffffffffu, v, 8);
            v += __shfl_xor_sync(0xffffffffu, v, 16);
            if (lane < 4) atomicAdd(&S[colBlock + n0 + nt * 8 + qcol + q], v);
        }
    }
}

// ---------------- logits GEMV: 2 rows/warp, + block max ----------------
__global__ void logits_kernel() {
    __shared__ float s[MD];
    __shared__ float wmax[8];
    int mat = blockIdx.x >> 9;
    const uint4* P = (const uint4*)(mat ? g_p2 : g_p1);
    const float* S = mat ? g_s1 : g_s2;
    float* L = g_logits + mat * AR;

    for (int i = threadIdx.x; i < MD; i += blockDim.x) s[i] = S[i];
    __syncthreads();

    int wid = threadIdx.x >> 5, lane = threadIdx.x & 31;
    int row0 = (blockIdx.x & 511) * 16 + wid * 2;
    const uint4* p0 = P + (size_t)row0 * 128;
    const uint4* p1 = P + (size_t)(row0 + 1) * 128;
    float acc0 = 0.0f, acc1 = 0.0f;
    #pragma unroll
    for (int i = 0; i < 4; i++) {
        int j = i * 32 + lane;
        uint4 u0 = p0[j];
        uint4 u1 = p1[j];
        float4 sv0 = *(const float4*)&s[8 * j];
        float4 sv1 = *(const float4*)&s[8 * j + 4];
        __nv_bfloat162 a0 = *(__nv_bfloat162*)&u0.x, a1 = *(__nv_bfloat162*)&u0.y;
        __nv_bfloat162 a2 = *(__nv_bfloat162*)&u0.z, a3 = *(__nv_bfloat162*)&u0.w;
        __nv_bfloat162 b0 = *(__nv_bfloat162*)&u1.x, b1 = *(__nv_bfloat162*)&u1.y;
        __nv_bfloat162 b2 = *(__nv_bfloat162*)&u1.z, b3 = *(__nv_bfloat162*)&u1.w;
        acc0 += __bfloat162float(a0.x) * sv0.x + __bfloat162float(a0.y) * sv0.y
              + __bfloat162float(a1.x) * sv0.z + __bfloat162float(a1.y) * sv0.w
              + __bfloat162float(a2.x) * sv1.x + __bfloat162float(a2.y) * sv1.y
              + __bfloat162float(a3.x) * sv1.z + __bfloat162float(a3.y) * sv1.w;
        acc1 += __bfloat162float(b0.x) * sv0.x + __bfloat162float(b0.y) * sv0.y
              + __bfloat162float(b1.x) * sv0.z + __bfloat162float(b1.y) * sv0.w
              + __bfloat162float(b2.x) * sv1.x + __bfloat162float(b2.y) * sv1.y
              + __bfloat162float(b3.x) * sv1.z + __bfloat162float(b3.y) * sv1.w;
    }
    #pragma unroll
    for (int o = 16; o > 0; o >>= 1) {
        acc0 += __shfl_down_sync(0xffffffffu, acc0, o);
        acc1 += __shfl_down_sync(0xffffffffu, acc1, o);
    }
    if (lane == 0) {
        L[row0] = acc0;
        L[row0 + 1] = acc1;
        wmax[wid] = fmaxf(acc0, acc1);
    }
    __syncthreads();
    if (threadIdx.x == 0) {
        float m = wmax[0];
        #pragma unroll
        for (int i = 1; i < 8; i++) m = fmaxf(m, wmax[i]);
        atomicMaxF(&g_max[mat], m);
    }
}

// ---------------- Z = sum exp(L - m) ----------------
__global__ void zsum_kernel() {
    __shared__ float wsum[32];
    int mat = blockIdx.y;
    float m = g_max[mat];
    int i = blockIdx.x * 1024 + threadIdx.x;
    float e = expf(g_logits[mat * AR + i] - m);
    #pragma unroll
    for (int o = 16; o > 0; o >>= 1) e += __shfl_down_sync(0xffffffffu, e, o);
    int wid = threadIdx.x >> 5, lane = threadIdx.x & 31;
    if (lane == 0) wsum[wid] = e;
    __syncthreads();
    if (wid == 0) {
        float v = wsum[lane];
        #pragma unroll
        for (int o = 16; o > 0; o >>= 1) v += __shfl_down_sync(0xffffffffu, v, o);
        if (lane == 0) atomicAdd(&g_z[mat], v);
    }
}

// ---------------- att = seq.T @ softmax(L) ----------------
__global__ void att_kernel(const float* __restrict__ seq1, const float* __restrict__ seq2,
                           float* __restrict__ out) {
    __shared__ float ws[512];
    int mat = blockIdx.z;
    const float* Sq = mat ? seq2 : seq1;
    const float* L = g_logits + mat * AR;
    int c = blockIdx.x * 256 + threadIdx.x;
    int r0 = blockIdx.y * 512;

    float m = g_max[mat];
    float invz = 1.0f / g_z[mat];
    for (int i = threadIdx.x; i < 512; i += 256)
        ws[i] = expf(L[r0 + i] - m) * invz;
    __syncthreads();

    float acc0 = 0.0f, acc1 = 0.0f;
    #pragma unroll 4
    for (int i = 0; i < 512; i += 2) {
        acc0 += Sq[(size_t)(r0 + i) * ED + c] * ws[i];
        acc1 += Sq[(size_t)(r0 + i + 1) * ED + c] * ws[i + 1];
    }
    atomicAdd(&out[mat * ED + c], acc0 + acc1);
}

// ---------------- launch ----------------
extern "C" void kernel_launch(void* const* d_in, const int* in_sizes, int n_in,
                              void* d_out, int out_size) {
    const float* seq1 = (const float*)d_in[0];
    const float* seq2 = (const float*)d_in[1];
    const float* ctx  = (const float*)d_in[2];
    const float* Wc1  = (const float*)d_in[3];
    const float* Wc2  = (const float*)d_in[4];
    const float* W1   = (const float*)d_in[5];
    const float* b1   = (const float*)d_in[6];
    const float* W2   = (const float*)d_in[7];
    const float* b2   = (const float*)d_in[8];
    float* out = (float*)d_out;

    __nv_bfloat16 *a1, *a2, *wb1, *wb2, *p1, *p2;
    float *bias1, *bias2, *s1, *s2;
    cudaGetSymbolAddress((void**)&a1, g_a1);
    cudaGetSymbolAddress((void**)&a2, g_a2);
    cudaGetSymbolAddress((void**)&wb1, g_wb1);
    cudaGetSymbolAddress((void**)&wb2, g_wb2);
    cudaGetSymbolAddress((void**)&p1, g_p1);
    cudaGetSymbolAddress((void**)&p2, g_p2);
    cudaGetSymbolAddress((void**)&bias1, g_bias1);
    cudaGetSymbolAddress((void**)&bias2, g_bias2);
    cudaGetSymbolAddress((void**)&s1, g_s1);
    cudaGetSymbolAddress((void**)&s2, g_s2);

    size_t smem = 2 * STAGE_BYTES + 128;
    cudaFuncSetAttribute(gemm_mma_kernel, cudaFuncAttributeMaxDynamicSharedMemorySize, (int)smem);

    zeroctx_kernel<<<256, 256>>>(ctx, Wc1, Wc2, b1, b2, out);
    conv_all_kernel<<<(TOT_F16 + 255) / 256, 256>>>(seq1, seq2, W1, W2);

    dim3 ggrid(MD / TN, AR / TM, 2);   // (8, 128, 2) = 2048 CTAs
    gemm_mma_kernel<<<ggrid, 256, smem>>>(a1, wb1, bias1, p1, s1,
                                          a2, wb2, bias2, p2, s2);

    logits_kernel<<<1024, 256>>>();
    zsum_kernel<<<dim3(8, 2), 1024>>>();
    att_kernel<<<dim3(ED / 256, AR / 512, 2), 256>>>(seq1, seq2, out);
}

// round 16
// speedup vs baseline: 1.0003x; 1.0003x over previous
#include <cuda_runtime.h>
#include <cuda_bf16.h>
#include <math.h>
#include <stdint.h>

#define AR 8192
#define ED 1024
#define MD 1024

// ---------------- device scratch ----------------
__device__ __nv_bfloat16 g_a1[(size_t)AR * ED];
__device__ __nv_bfloat16 g_a2[(size_t)AR * ED];
__device__ __nv_bfloat16 g_wb1[(size_t)MD * ED];
__device__ __nv_bfloat16 g_wb2[(size_t)MD * ED];
__device__ __nv_bfloat16 g_p1[(size_t)AR * MD];
__device__ __nv_bfloat16 g_p2[(size_t)AR * MD];
__device__ float g_s1[MD];
__device__ float g_s2[MD];
__device__ float g_bias1[MD];
__device__ float g_bias2[MD];
__device__ float g_logits[2 * AR];
__device__ float g_max[2];
__device__ float g_z[2];

__device__ __forceinline__ float elu1(float x) { return x > 0.0f ? x : expm1f(x); }

__device__ __forceinline__ void atomicMaxF(float* a, float v) {
    if (v >= 0.0f) atomicMax((int*)a, __float_as_int(v));
    else atomicMin((unsigned int*)a, __float_as_uint(v));
}

__device__ __forceinline__ uint32_t smem_u32(const void* p) {
    uint32_t a;
    asm("{ .reg .u64 t; cvta.to.shared.u64 t, %1; cvt.u32.u64 %0, t; }" : "=r"(a) : "l"(p));
    return a;
}
#define CP_ASYNC16(dst, src) \
    asm volatile("cp.async.cg.shared.global [%0], [%1], 16;" :: "r"(dst), "l"(src))
#define CP_COMMIT() asm volatile("cp.async.commit_group;" ::: "memory")
#define CP_WAIT1()  asm volatile("cp.async.wait_group 1;" ::: "memory")
#define LDMATRIX_X4(r0, r1, r2, r3, addr) \
    asm volatile("ldmatrix.sync.aligned.m8n8.x4.shared.b16 {%0,%1,%2,%3}, [%4];" \
        : "=r"(r0), "=r"(r1), "=r"(r2), "=r"(r3) : "r"(addr))
#define MMA16816(c0, c1, c2, c3, a0, a1, a2, a3, b0, b1) \
    asm volatile("mma.sync.aligned.m16n8k16.row.col.f32.bf16.bf16.f32 " \
        "{%0,%1,%2,%3}, {%4,%5,%6,%7}, {%8,%9}, {%0,%1,%2,%3};" \
        : "+f"(c0), "+f"(c1), "+f"(c2), "+f"(c3) \
        : "r"(a0), "r"(a1), "r"(a2), "r"(a3), "r"(b0), "r"(b1))

// ---------------- merged conv: all 4 tensors f32 -> bf16, 32 f32/thread ----
// 8 independent LDG.128 issued up-front (MLP=8), then 4 STG.128.
#define SEQ_G32 (AR * ED / 32)    // 262144 groups per seq tensor
#define W_G32   (MD * ED / 32)    // 32768 groups per W tensor
#define TOT_G32 (2 * SEQ_G32 + 2 * W_G32)

__global__ void conv_all_kernel(const float* __restrict__ seq1, const float* __restrict__ seq2,
                                const float* __restrict__ W1, const float* __restrict__ W2) {
    int i = blockIdx.x * blockDim.x + threadIdx.x;
    if (i >= TOT_G32) return;
    const float* src;
    __nv_bfloat16* dst;
    int off;
    if (i < SEQ_G32)                 { src = seq1; dst = g_a1;  off = i; }
    else if (i < 2 * SEQ_G32)        { src = seq2; dst = g_a2;  off = i - SEQ_G32; }
    else if (i < 2 * SEQ_G32 + W_G32){ src = W1;   dst = g_wb1; off = i - 2 * SEQ_G32; }
    else                             { src = W2;   dst = g_wb2; off = i - 2 * SEQ_G32 - W_G32; }
    const float4* s4 = (const float4*)src + 8 * (size_t)off;
    // front-batch 8 independent 16B loads
    float4 v0 = s4[0], v1 = s4[1], v2 = s4[2], v3 = s4[3];
    float4 v4 = s4[4], v5 = s4[5], v6 = s4[6], v7 = s4[7];
    uint4 o0, o1, o2, o3;
    asm("cvt.rn.bf16x2.f32 %0, %1, %2;" : "=r"(o0.x) : "f"(v0.y), "f"(v0.x));
    asm("cvt.rn.bf16x2.f32 %0, %1, %2;" : "=r"(o0.y) : "f"(v0.w), "f"(v0.z));
    asm("cvt.rn.bf16x2.f32 %0, %1, %2;" : "=r"(o0.z) : "f"(v1.y), "f"(v1.x));
    asm("cvt.rn.bf16x2.f32 %0, %1, %2;" : "=r"(o0.w) : "f"(v1.w), "f"(v1.z));
    asm("cvt.rn.bf16x2.f32 %0, %1, %2;" : "=r"(o1.x) : "f"(v2.y), "f"(v2.x));
    asm("cvt.rn.bf16x2.f32 %0, %1, %2;" : "=r"(o1.y) : "f"(v2.w), "f"(v2.z));
    asm("cvt.rn.bf16x2.f32 %0, %1, %2;" : "=r"(o1.z) : "f"(v3.y), "f"(v3.x));
    asm("cvt.rn.bf16x2.f32 %0, %1, %2;" : "=r"(o1.w) : "f"(v3.w), "f"(v3.z));
    asm("cvt.rn.bf16x2.f32 %0, %1, %2;" : "=r"(o2.x) : "f"(v4.y), "f"(v4.x));
    asm("cvt.rn.bf16x2.f32 %0, %1, %2;" : "=r"(o2.y) : "f"(v4.w), "f"(v4.z));
    asm("cvt.rn.bf16x2.f32 %0, %1, %2;" : "=r"(o2.z) : "f"(v5.y), "f"(v5.x));
    asm("cvt.rn.bf16x2.f32 %0, %1, %2;" : "=r"(o2.w) : "f"(v5.w), "f"(v5.z));
    asm("cvt.rn.bf16x2.f32 %0, %1, %2;" : "=r"(o3.x) : "f"(v6.y), "f"(v6.x));
    asm("cvt.rn.bf16x2.f32 %0, %1, %2;" : "=r"(o3.y) : "f"(v6.w), "f"(v6.z));
    asm("cvt.rn.bf16x2.f32 %0, %1, %2;" : "=r"(o3.z) : "f"(v7.y), "f"(v7.x));
    asm("cvt.rn.bf16x2.f32 %0, %1, %2;" : "=r"(o3.w) : "f"(v7.w), "f"(v7.z));
    uint4* d4 = (uint4*)dst + 4 * (size_t)off;
    d4[0] = o0; d4[1] = o1; d4[2] = o2; d4[3] = o3;
}

// ---------------- zero + ctx GEMV fused ----------------
__global__ void zeroctx_kernel(const float* __restrict__ ctx,
                               const float* __restrict__ Wc1, const float* __restrict__ Wc2,
                               const float* __restrict__ b1, const float* __restrict__ b2,
                               float* __restrict__ out) {
    int gid = blockIdx.x * blockDim.x + threadIdx.x;
    if (gid < MD) { g_s1[gid] = 0.0f; g_s2[gid] = 0.0f; }
    if (gid < 2 * ED) out[gid] = 0.0f;
    if (gid < 2) { g_max[gid] = -INFINITY; g_z[gid] = 0.0f; }

    int g = gid >> 5;
    int lane = gid & 31;
    int mat = g >> 10, row = g & 1023;
    const float* W = mat ? Wc2 : Wc1;
    const float* b = mat ? b2 : b1;
    float* o = mat ? g_bias2 : g_bias1;
    float acc = 0.0f;
    const float* wr = W + (size_t)row * ED;
    for (int k = lane; k < ED; k += 32) acc += wr[k] * ctx[k];
    #pragma unroll
    for (int off = 16; off > 0; off >>= 1) acc += __shfl_down_sync(0xffffffffu, acc, off);
    if (lane == 0) o[row] = b[row] + acc;
}

// ---------------- bf16 mma.sync GEMM (champion core, unchanged) ------------
#define BK 64
#define NCHUNK (ED / BK)                 // 16
#define STAGE_BYTES (2 * 128 * 128)      // A 16KB + B 16KB

__global__ void __launch_bounds__(256, 2)
gemm_mma_kernel(const __nv_bfloat16* __restrict__ A1, const __nv_bfloat16* __restrict__ B1,
                const float* __restrict__ bias1v, __nv_bfloat16* __restrict__ P1,
                float* __restrict__ S1,
                const __nv_bfloat16* __restrict__ A2, const __nv_bfloat16* __restrict__ B2,
                const float* __restrict__ bias2v, __nv_bfloat16* __restrict__ P2,
                float* __restrict__ S2) {
    extern __shared__ __align__(128) char dyn[];
    __shared__ float bias_s[128];

    const int z = blockIdx.z;
    const __nv_bfloat16* A = z ? A2 : A1;
    const __nv_bfloat16* W = z ? B2 : B1;
    const float* bias = z ? bias2v : bias1v;
    __nv_bfloat16* P = z ? P2 : P1;
    float* S = z ? S2 : S1;

    const int tid = threadIdx.x;
    const int wid = tid >> 5, lane = tid & 31;
    const int rowBlock = blockIdx.y * 128;
    const int colBlock = blockIdx.x * 128;

    uint32_t sbase = (smem_u32(dyn) + 127u) & ~127u;

    if (tid < 128) bias_s[tid] = bias[colBlock + tid];

    const int m0 = (wid & 1) * 64;
    const int n0 = (wid >> 1) * 32;

    float acc[4][4][4];
    #pragma unroll
    for (int i = 0; i < 4; i++)
        #pragma unroll
        for (int j = 0; j < 4; j++)
            #pragma unroll
            for (int q = 0; q < 4; q++) acc[i][j][q] = 0.0f;

    auto load_chunk = [&](int chunk, int stage) {
        const int k0 = chunk * BK;
        uint32_t ab = sbase + stage * STAGE_BYTES;
        uint32_t bb = ab + 16384;
        #pragma unroll
        for (int l = 0; l < 4; l++) {
            int i = tid + l * 256;
            int r = i >> 3, c = i & 7;
            uint32_t dst = ab + (uint32_t)(r * 128) + (uint32_t)((c ^ (r & 7)) << 4);
            CP_ASYNC16(dst, A + (size_t)(rowBlock + r) * ED + k0 + c * 8);
        }
        #pragma unroll
        for (int l = 0; l < 4; l++) {
            int i = tid + l * 256;
            int r = i >> 3, c = i & 7;
            uint32_t dst = bb + (uint32_t)(r * 128) + (uint32_t)((c ^ (r & 7)) << 4);
            CP_ASYNC16(dst, W + (size_t)(colBlock + r) * ED + k0 + c * 8);
        }
        CP_COMMIT();
    };

    load_chunk(0, 0);
    load_chunk(1, 1);

    const int lr = lane & 7, sub = lane >> 3;
    int arow[4], brow[2];
    uint32_t aswz[4], bswz[2];
    #pragma unroll
    for (int mi = 0; mi < 4; mi++) {
        int r = m0 + mi * 16 + ((sub & 1) << 3) + lr;
        arow[mi] = r * 128; aswz[mi] = (uint32_t)(r & 7);
    }
    const uint32_t achunkbit = (uint32_t)(sub >> 1);
    #pragma unroll
    for (int p = 0; p < 2; p++) {
        int r = n0 + p * 16 + ((sub >> 1) << 3) + lr;
        brow[p] = r * 128; bswz[p] = (uint32_t)(r & 7);
    }
    const uint32_t bchunkbit = (uint32_t)(sub & 1);

    for (int ch = 0; ch < NCHUNK; ch++) {
        const int s = ch & 1;
        CP_WAIT1();
        __syncthreads();
        uint32_t ab = sbase + s * STAGE_BYTES;
        uint32_t bb = ab + 16384;

        #pragma unroll
        for (int ks = 0; ks < 4; ks++) {
            uint32_t a[4][4], b[8];
            #pragma unroll
            for (int mi = 0; mi < 4; mi++) {
                uint32_t addr = ab + (uint32_t)arow[mi] +
                                ((((uint32_t)(ks << 1) | achunkbit) ^ aswz[mi]) << 4);
                LDMATRIX_X4(a[mi][0], a[mi][1], a[mi][2], a[mi][3], addr);
            }
            #pragma unroll
            for (int p = 0; p < 2; p++) {
                uint32_t addr = bb + (uint32_t)brow[p] +
                                ((((uint32_t)(ks << 1) | bchunkbit) ^ bswz[p]) << 4);
                LDMATRIX_X4(b[p * 4 + 0], b[p * 4 + 1], b[p * 4 + 2], b[p * 4 + 3], addr);
            }
            #pragma unroll
            for (int mi = 0; mi < 4; mi++)
                #pragma unroll
                for (int nt = 0; nt < 4; nt++)
                    MMA16816(acc[mi][nt][0], acc[mi][nt][1], acc[mi][nt][2], acc[mi][nt][3],
                             a[mi][0], a[mi][1], a[mi][2], a[mi][3],
                             b[nt * 2], b[nt * 2 + 1]);
        }
        __syncthreads();
        if (ch < NCHUNK - 2) load_chunk(ch + 2, s);
        else CP_COMMIT();
    }

    // epilogue: bias + elu -> bf16 stores, fused column sums
    const int qrow = lane >> 2;
    const int qcol = (lane & 3) * 2;
    float csum[4][2];
    #pragma unroll
    for (int nt = 0; nt < 4; nt++) { csum[nt][0] = 0.0f; csum[nt][1] = 0.0f; }

    #pragma unroll
    for (int mi = 0; mi < 4; mi++) {
        #pragma unroll
        for (int nt = 0; nt < 4; nt++) {
            int col = n0 + nt * 8 + qcol;
            float bv0 = bias_s[col], bv1 = bias_s[col + 1];
            int r0 = rowBlock + m0 + mi * 16 + qrow;
            float x0 = elu1(acc[mi][nt][0] + bv0);
            float x1 = elu1(acc[mi][nt][1] + bv1);
            float x2 = elu1(acc[mi][nt][2] + bv0);
            float x3 = elu1(acc[mi][nt][3] + bv1);
            csum[nt][0] += x0 + x2;
            csum[nt][1] += x1 + x3;
            uint32_t p01, p23;
            asm("cvt.rn.bf16x2.f32 %0, %1, %2;" : "=r"(p01) : "f"(x1), "f"(x0));
            asm("cvt.rn.bf16x2.f32 %0, %1, %2;" : "=r"(p23) : "f"(x3), "f"(x2));
            *(uint32_t*)(P + (size_t)r0 * MD + colBlock + col) = p01;
            *(uint32_t*)(P + (size_t)(r0 + 8) * MD + colBlock + col) = p23;
        }
    }
    #pragma unroll
    for (int nt = 0; nt < 4; nt++) {
        #pragma unroll
        for (int q = 0; q < 2; q++) {
            float v = csum[nt][q];
            v += __shfl_xor_sync(0xffffffffu, v, 4);
            v += __shfl_xor_sync(0xffffffffu, v, 8);
            v += __shfl_xor_sync(0xffffffffu, v, 16);
            if (lane < 4) atomicAdd(&S[colBlock + n0 + nt * 8 + qcol + q], v);
        }
    }
}

// ---------------- logits GEMV: 2 rows/warp, + block max ----------------
__global__ void logits_kernel() {
    __shared__ float s[MD];
    __shared__ float wmax[8];
    int mat = blockIdx.x >> 9;
    const uint4* P = (const uint4*)(mat ? g_p2 : g_p1);
    const float* S = mat ? g_s1 : g_s2;
    float* L = g_logits + mat * AR;

    for (int i = threadIdx.x; i < MD; i += blockDim.x) s[i] = S[i];
    __syncthreads();

    int wid = threadIdx.x >> 5, lane = threadIdx.x & 31;
    int row0 = (blockIdx.x & 511) * 16 + wid * 2;
    const uint4* p0 = P + (size_t)row0 * 128;
    const uint4* p1 = P + (size_t)(row0 + 1) * 128;
    float acc0 = 0.0f, acc1 = 0.0f;
    #pragma unroll
    for (int i = 0; i < 4; i++) {
        int j = i * 32 + lane;
        uint4 u0 = p0[j];
        uint4 u1 = p1[j];
        float4 sv0 = *(const float4*)&s[8 * j];
        float4 sv1 = *(const float4*)&s[8 * j + 4];
        __nv_bfloat162 a0 = *(__nv_bfloat162*)&u0.x, a1 = *(__nv_bfloat162*)&u0.y;
        __nv_bfloat162 a2 = *(__nv_bfloat162*)&u0.z, a3 = *(__nv_bfloat162*)&u0.w;
        __nv_bfloat162 b0 = *(__nv_bfloat162*)&u1.x, b1 = *(__nv_bfloat162*)&u1.y;
        __nv_bfloat162 b2 = *(__nv_bfloat162*)&u1.z, b3 = *(__nv_bfloat162*)&u1.w;
        acc0 += __bfloat162float(a0.x) * sv0.x + __bfloat162float(a0.y) * sv0.y
              + __bfloat162float(a1.x) * sv0.z + __bfloat162float(a1.y) * sv0.w
              + __bfloat162float(a2.x) * sv1.x + __bfloat162float(a2.y) * sv1.y
              + __bfloat162float(a3.x) * sv1.z + __bfloat162float(a3.y) * sv1.w;
        acc1 += __bfloat162float(b0.x) * sv0.x + __bfloat162float(b0.y) * sv0.y
              + __bfloat162float(b1.x) * sv0.z + __bfloat162float(b1.y) * sv0.w
              + __bfloat162float(b2.x) * sv1.x + __bfloat162float(b2.y) * sv1.y
              + __bfloat162float(b3.x) * sv1.z + __bfloat162float(b3.y) * sv1.w;
    }
    #pragma unroll
    for (int o = 16; o > 0; o >>= 1) {
        acc0 += __shfl_down_sync(0xffffffffu, acc0, o);
        acc1 += __shfl_down_sync(0xffffffffu, acc1, o);
    }
    if (lane == 0) {
        L[row0] = acc0;
        L[row0 + 1] = acc1;
        wmax[wid] = fmaxf(acc0, acc1);
    }
    __syncthreads();
    if (threadIdx.x == 0) {
        float m = wmax[0];
        #pragma unroll
        for (int i = 1; i < 8; i++) m = fmaxf(m, wmax[i]);
        atomicMaxF(&g_max[mat], m);
    }
}

// ---------------- Z = sum exp(L - m) ----------------
__global__ void zsum_kernel() {
    __shared__ float wsum[32];
    int mat = blockIdx.y;
    float m = g_max[mat];
    int i = blockIdx.x * 1024 + threadIdx.x;
    float e = expf(g_logits[mat * AR + i] - m);
    #pragma unroll
    for (int o = 16; o > 0; o >>= 1) e += __shfl_down_sync(0xffffffffu, e, o);
    int wid = threadIdx.x >> 5, lane = threadIdx.x & 31;
    if (lane == 0) wsum[wid] = e;
    __syncthreads();
    if (wid == 0) {
        float v = wsum[lane];
        #pragma unroll
        for (int o = 16; o > 0; o >>= 1) v += __shfl_down_sync(0xffffffffu, v, o);
        if (lane == 0) atomicAdd(&g_z[mat], v);
    }
}

// ---------------- att = seq.T @ softmax(L) ----------------
__global__ void att_kernel(const float* __restrict__ seq1, const float* __restrict__ seq2,
                           float* __restrict__ out) {
    __shared__ float ws[512];
    int mat = blockIdx.z;
    const float* Sq = mat ? seq2 : seq1;
    const float* L = g_logits + mat * AR;
    int c = blockIdx.x * 256 + threadIdx.x;
    int r0 = blockIdx.y * 512;

    float m = g_max[mat];
    float invz = 1.0f / g_z[mat];
    for (int i = threadIdx.x; i < 512; i += 256)
        ws[i] = expf(L[r0 + i] - m) * invz;
    __syncthreads();

    float acc0 = 0.0f, acc1 = 0.0f;
    #pragma unroll 4
    for (int i = 0; i < 512; i += 2) {
        acc0 += Sq[(size_t)(r0 + i) * ED + c] * ws[i];
        acc1 += Sq[(size_t)(r0 + i + 1) * ED + c] * ws[i + 1];
    }
    atomicAdd(&out[mat * ED + c], acc0 + acc1);
}

// ---------------- launch ----------------
extern "C" void kernel_launch(void* const* d_in, const int* in_sizes, int n_in,
                              void* d_out, int out_size) {
    const float* seq1 = (const float*)d_in[0];
    const float* seq2 = (const float*)d_in[1];
    const float* ctx  = (const float*)d_in[2];
    const float* Wc1  = (const float*)d_in[3];
    const float* Wc2  = (const float*)d_in[4];
    const float* W1   = (const float*)d_in[5];
    const float* b1   = (const float*)d_in[6];
    const float* W2   = (const float*)d_in[7];
    const float* b2   = (const float*)d_in[8];
    float* out = (float*)d_out;

    __nv_bfloat16 *a1, *a2, *wb1, *wb2, *p1, *p2;
    float *bias1, *bias2, *s1, *s2;
    cudaGetSymbolAddress((void**)&a1, g_a1);
    cudaGetSymbolAddress((void**)&a2, g_a2);
    cudaGetSymbolAddress((void**)&wb1, g_wb1);
    cudaGetSymbolAddress((void**)&wb2, g_wb2);
    cudaGetSymbolAddress((void**)&p1, g_p1);
    cudaGetSymbolAddress((void**)&p2, g_p2);
    cudaGetSymbolAddress((void**)&bias1, g_bias1);
    cudaGetSymbolAddress((void**)&bias2, g_bias2);
    cudaGetSymbolAddress((void**)&s1, g_s1);
    cudaGetSymbolAddress((void**)&s2, g_s2);

    size_t smem = 2 * STAGE_BYTES + 128;
    cudaFuncSetAttribute(gemm_mma_kernel, cudaFuncAttributeMaxDynamicSharedMemorySize, (int)smem);

    zeroctx_kernel<<<256, 256>>>(ctx, Wc1, Wc2, b1, b2, out);
    conv_all_kernel<<<(TOT_G32 + 255) / 256, 256>>>(seq1, seq2, W1, W2);

    dim3 ggrid(MD / 128, AR / 128, 2);   // 1024 CTAs
    gemm_mma_kernel<<<ggrid, 256, smem>>>(a1, wb1, bias1, p1, s1,
                                          a2, wb2, bias2, p2, s2);

    logits_kernel<<<1024, 256>>>();
    zsum_kernel<<<dim3(8, 2), 1024>>>();
    att_kernel<<<dim3(ED / 256, AR / 512, 2), 256>>>(seq1, seq2, out);
}

// round 17
// speedup vs baseline: 1.0584x; 1.0580x over previous
#include <cuda_runtime.h>
#include <cuda_bf16.h>
#include <math.h>
#include <stdint.h>

#define AR 8192
#define ED 1024
#define MD 1024

// ---------------- device scratch ----------------
__device__ __nv_bfloat16 g_a1[(size_t)AR * ED];
__device__ __nv_bfloat16 g_a2[(size_t)AR * ED];
__device__ __nv_bfloat16 g_wb1[(size_t)MD * ED];
__device__ __nv_bfloat16 g_wb2[(size_t)MD * ED];
__device__ __nv_bfloat16 g_p1[(size_t)AR * MD];
__device__ __nv_bfloat16 g_p2[(size_t)AR * MD];
__device__ float g_s1[MD];
__device__ float g_s2[MD];
__device__ float g_bias1[MD];
__device__ float g_bias2[MD];
__device__ float g_logits[2 * AR];
__device__ float g_max[2];
__device__ float g_z[2];

__device__ __forceinline__ float elu1(float x) { return x > 0.0f ? x : expm1f(x); }

__device__ __forceinline__ void atomicMaxF(float* a, float v) {
    if (v >= 0.0f) atomicMax((int*)a, __float_as_int(v));
    else atomicMin((unsigned int*)a, __float_as_uint(v));
}

__device__ __forceinline__ uint32_t smem_u32(const void* p) {
    uint32_t a;
    asm("{ .reg .u64 t; cvta.to.shared.u64 t, %1; cvt.u32.u64 %0, t; }" : "=r"(a) : "l"(p));
    return a;
}
#define CP_ASYNC16(dst, src) \
    asm volatile("cp.async.cg.shared.global [%0], [%1], 16;" :: "r"(dst), "l"(src))
#define CP_COMMIT() asm volatile("cp.async.commit_group;" ::: "memory")
#define CP_WAIT1()  asm volatile("cp.async.wait_group 1;" ::: "memory")
#define LDMATRIX_X4(r0, r1, r2, r3, addr) \
    asm volatile("ldmatrix.sync.aligned.m8n8.x4.shared.b16 {%0,%1,%2,%3}, [%4];" \
        : "=r"(r0), "=r"(r1), "=r"(r2), "=r"(r3) : "r"(addr))
#define MMA16816(c0, c1, c2, c3, a0, a1, a2, a3, b0, b1) \
    asm volatile("mma.sync.aligned.m16n8k16.row.col.f32.bf16.bf16.f32 " \
        "{%0,%1,%2,%3}, {%4,%5,%6,%7}, {%8,%9}, {%0,%1,%2,%3};" \
        : "+f"(c0), "+f"(c1), "+f"(c2), "+f"(c3) \
        : "r"(a0), "r"(a1), "r"(a2), "r"(a3), "r"(b0), "r"(b1))

// ---------------- merged conv: all 4 tensors f32 -> bf16, 16 f32/thread ----
#define SEQ_F16 (AR * ED / 16)    // 524288
#define W_F16   (MD * ED / 16)    // 65536
#define TOT_F16 (2 * SEQ_F16 + 2 * W_F16)

__global__ void conv_all_kernel(const float* __restrict__ seq1, const float* __restrict__ seq2,
                                const float* __restrict__ W1, const float* __restrict__ W2) {
    int i = blockIdx.x * blockDim.x + threadIdx.x;
    if (i >= TOT_F16) return;
    const float* src;
    __nv_bfloat16* dst;
    int off;
    if (i < SEQ_F16)                 { src = seq1; dst = g_a1;  off = i; }
    else if (i < 2 * SEQ_F16)        { src = seq2; dst = g_a2;  off = i - SEQ_F16; }
    else if (i < 2 * SEQ_F16 + W_F16){ src = W1;   dst = g_wb1; off = i - 2 * SEQ_F16; }
    else                             { src = W2;   dst = g_wb2; off = i - 2 * SEQ_F16 - W_F16; }
    const float4* s4 = (const float4*)src + 4 * (size_t)off;
    float4 v0 = s4[0], v1 = s4[1], v2 = s4[2], v3 = s4[3];
    uint4 o0, o1;
    asm("cvt.rn.bf16x2.f32 %0, %1, %2;" : "=r"(o0.x) : "f"(v0.y), "f"(v0.x));
    asm("cvt.rn.bf16x2.f32 %0, %1, %2;" : "=r"(o0.y) : "f"(v0.w), "f"(v0.z));
    asm("cvt.rn.bf16x2.f32 %0, %1, %2;" : "=r"(o0.z) : "f"(v1.y), "f"(v1.x));
    asm("cvt.rn.bf16x2.f32 %0, %1, %2;" : "=r"(o0.w) : "f"(v1.w), "f"(v1.z));
    asm("cvt.rn.bf16x2.f32 %0, %1, %2;" : "=r"(o1.x) : "f"(v2.y), "f"(v2.x));
    asm("cvt.rn.bf16x2.f32 %0, %1, %2;" : "=r"(o1.y) : "f"(v2.w), "f"(v2.z));
    asm("cvt.rn.bf16x2.f32 %0, %1, %2;" : "=r"(o1.z) : "f"(v3.y), "f"(v3.x));
    asm("cvt.rn.bf16x2.f32 %0, %1, %2;" : "=r"(o1.w) : "f"(v3.w), "f"(v3.z));
    ((uint4*)dst)[2 * (size_t)off] = o0;
    ((uint4*)dst)[2 * (size_t)off + 1] = o1;
}

// ---------------- zero + ctx GEMV fused ----------------
__global__ void zeroctx_kernel(const float* __restrict__ ctx,
                               const float* __restrict__ Wc1, const float* __restrict__ Wc2,
                               const float* __restrict__ b1, const float* __restrict__ b2,
                               float* __restrict__ out) {
    int gid = blockIdx.x * blockDim.x + threadIdx.x;
    if (gid < MD) { g_s1[gid] = 0.0f; g_s2[gid] = 0.0f; }
    if (gid < 2 * ED) out[gid] = 0.0f;
    if (gid < 2) { g_max[gid] = -INFINITY; g_z[gid] = 0.0f; }

    int g = gid >> 5;
    int lane = gid & 31;
    int mat = g >> 10, row = g & 1023;
    const float* W = mat ? Wc2 : Wc1;
    const float* b = mat ? b2 : b1;
    float* o = mat ? g_bias2 : g_bias1;
    float acc = 0.0f;
    const float* wr = W + (size_t)row * ED;
    for (int k = lane; k < ED; k += 32) acc += wr[k] * ctx[k];
    #pragma unroll
    for (int off = 16; off > 0; off >>= 1) acc += __shfl_down_sync(0xffffffffu, acc, off);
    if (lane == 0) o[row] = b[row] + acc;
}

// ---------------- bf16 mma.sync GEMM (champion core) ----------------------
#define BK 64
#define NCHUNK (ED / BK)                 // 16
#define STAGE_BYTES (2 * 128 * 128)      // A 16KB + B 16KB

__global__ void __launch_bounds__(256, 2)
gemm_mma_kernel(const __nv_bfloat16* __restrict__ A1, const __nv_bfloat16* __restrict__ B1,
                const float* __restrict__ bias1v, __nv_bfloat16* __restrict__ P1,
                float* __restrict__ S1,
                const __nv_bfloat16* __restrict__ A2, const __nv_bfloat16* __restrict__ B2,
                const float* __restrict__ bias2v, __nv_bfloat16* __restrict__ P2,
                float* __restrict__ S2) {
    extern __shared__ __align__(128) char dyn[];
    __shared__ float bias_s[128];

    const int z = blockIdx.z;
    const __nv_bfloat16* A = z ? A2 : A1;
    const __nv_bfloat16* W = z ? B2 : B1;
    const float* bias = z ? bias2v : bias1v;
    __nv_bfloat16* P = z ? P2 : P1;
    float* S = z ? S2 : S1;

    const int tid = threadIdx.x;
    const int wid = tid >> 5, lane = tid & 31;
    const int rowBlock = blockIdx.y * 128;
    const int colBlock = blockIdx.x * 128;

    uint32_t sbase = (smem_u32(dyn) + 127u) & ~127u;

    if (tid < 128) bias_s[tid] = bias[colBlock + tid];

    const int m0 = (wid & 1) * 64;
    const int n0 = (wid >> 1) * 32;

    float acc[4][4][4];
    #pragma unroll
    for (int i = 0; i < 4; i++)
        #pragma unroll
        for (int j = 0; j < 4; j++)
            #pragma unroll
            for (int q = 0; q < 4; q++) acc[i][j][q] = 0.0f;

    auto load_chunk = [&](int chunk, int stage) {
        const int k0 = chunk * BK;
        uint32_t ab = sbase + stage * STAGE_BYTES;
        uint32_t bb = ab + 16384;
        #pragma unroll
        for (int l = 0; l < 4; l++) {
            int i = tid + l * 256;
            int r = i >> 3, c = i & 7;
            uint32_t dst = ab + (uint32_t)(r * 128) + (uint32_t)((c ^ (r & 7)) << 4);
            CP_ASYNC16(dst, A + (size_t)(rowBlock + r) * ED + k0 + c * 8);
        }
        #pragma unroll
        for (int l = 0; l < 4; l++) {
            int i = tid + l * 256;
            int r = i >> 3, c = i & 7;
            uint32_t dst = bb + (uint32_t)(r * 128) + (uint32_t)((c ^ (r & 7)) << 4);
            CP_ASYNC16(dst, W + (size_t)(colBlock + r) * ED + k0 + c * 8);
        }
        CP_COMMIT();
    };

    load_chunk(0, 0);
    load_chunk(1, 1);

    const int lr = lane & 7, sub = lane >> 3;
    int arow[4], brow[2];
    uint32_t aswz[4], bswz[2];
    #pragma unroll
    for (int mi = 0; mi < 4; mi++) {
        int r = m0 + mi * 16 + ((sub & 1) << 3) + lr;
        arow[mi] = r * 128; aswz[mi] = (uint32_t)(r & 7);
    }
    const uint32_t achunkbit = (uint32_t)(sub >> 1);
    #pragma unroll
    for (int p = 0; p < 2; p++) {
        int r = n0 + p * 16 + ((sub >> 1) << 3) + lr;
        brow[p] = r * 128; bswz[p] = (uint32_t)(r & 7);
    }
    const uint32_t bchunkbit = (uint32_t)(sub & 1);

    for (int ch = 0; ch < NCHUNK; ch++) {
        const int s = ch & 1;
        CP_WAIT1();
        __syncthreads();
        uint32_t ab = sbase + s * STAGE_BYTES;
        uint32_t bb = ab + 16384;

        #pragma unroll
        for (int ks = 0; ks < 4; ks++) {
            uint32_t a[4][4], b[8];
            #pragma unroll
            for (int mi = 0; mi < 4; mi++) {
                uint32_t addr = ab + (uint32_t)arow[mi] +
                                ((((uint32_t)(ks << 1) | achunkbit) ^ aswz[mi]) << 4);
                LDMATRIX_X4(a[mi][0], a[mi][1], a[mi][2], a[mi][3], addr);
            }
            #pragma unroll
            for (int p = 0; p < 2; p++) {
                uint32_t addr = bb + (uint32_t)brow[p] +
                                ((((uint32_t)(ks << 1) | bchunkbit) ^ bswz[p]) << 4);
                LDMATRIX_X4(b[p * 4 + 0], b[p * 4 + 1], b[p * 4 + 2], b[p * 4 + 3], addr);
            }
            #pragma unroll
            for (int mi = 0; mi < 4; mi++)
                #pragma unroll
                for (int nt = 0; nt < 4; nt++)
                    MMA16816(acc[mi][nt][0], acc[mi][nt][1], acc[mi][nt][2], acc[mi][nt][3],
                             a[mi][0], a[mi][1], a[mi][2], a[mi][3],
                             b[nt * 2], b[nt * 2 + 1]);
        }
        __syncthreads();
        if (ch < NCHUNK - 2) load_chunk(ch + 2, s);
        else CP_COMMIT();
    }

    // epilogue: bias + elu -> bf16 stores, fused column sums
    const int qrow = lane >> 2;
    const int qcol = (lane & 3) * 2;
    float csum[4][2];
    #pragma unroll
    for (int nt = 0; nt < 4; nt++) { csum[nt][0] = 0.0f; csum[nt][1] = 0.0f; }

    #pragma unroll
    for (int mi = 0; mi < 4; mi++) {
        #pragma unroll
        for (int nt = 0; nt < 4; nt++) {
            int col = n0 + nt * 8 + qcol;
            float bv0 = bias_s[col], bv1 = bias_s[col + 1];
            int r0 = rowBlock + m0 + mi * 16 + qrow;
            float x0 = elu1(acc[mi][nt][0] + bv0);
            float x1 = elu1(acc[mi][nt][1] + bv1);
            float x2 = elu1(acc[mi][nt][2] + bv0);
            float x3 = elu1(acc[mi][nt][3] + bv1);
            csum[nt][0] += x0 + x2;
            csum[nt][1] += x1 + x3;
            uint32_t p01, p23;
            asm("cvt.rn.bf16x2.f32 %0, %1, %2;" : "=r"(p01) : "f"(x1), "f"(x0));
            asm("cvt.rn.bf16x2.f32 %0, %1, %2;" : "=r"(p23) : "f"(x3), "f"(x2));
            *(uint32_t*)(P + (size_t)r0 * MD + colBlock + col) = p01;
            *(uint32_t*)(P + (size_t)(r0 + 8) * MD + colBlock + col) = p23;
        }
    }
    #pragma unroll
    for (int nt = 0; nt < 4; nt++) {
        #pragma unroll
        for (int q = 0; q < 2; q++) {
            float v = csum[nt][q];
            v += __shfl_xor_sync(0xffffffffu, v, 4);
            v += __shfl_xor_sync(0xffffffffu, v, 8);
            v += __shfl_xor_sync(0xffffffffu, v, 16);
            if (lane < 4) atomicAdd(&S[colBlock + n0 + nt * 8 + qcol + q], v);
        }
    }
}

// ---------------- logits GEMV: 2 rows/warp, + block max ----------------
__global__ void logits_kernel() {
    __shared__ float s[MD];
    __shared__ float wmax[8];
    int mat = blockIdx.x >> 9;
    const uint4* P = (const uint4*)(mat ? g_p2 : g_p1);
    const float* S = mat ? g_s1 : g_s2;
    float* L = g_logits + mat * AR;

    for (int i = threadIdx.x; i < MD; i += blockDim.x) s[i] = S[i];
    __syncthreads();

    int wid = threadIdx.x >> 5, lane = threadIdx.x & 31;
    int row0 = (blockIdx.x & 511) * 16 + wid * 2;
    const uint4* p0 = P + (size_t)row0 * 128;
    const uint4* p1 = P + (size_t)(row0 + 1) * 128;
    float acc0 = 0.0f, acc1 = 0.0f;
    #pragma unroll
    for (int i = 0; i < 4; i++) {
        int j = i * 32 + lane;
        uint4 u0 = p0[j];
        uint4 u1 = p1[j];
        float4 sv0 = *(const float4*)&s[8 * j];
        float4 sv1 = *(const float4*)&s[8 * j + 4];
        __nv_bfloat162 a0 = *(__nv_bfloat162*)&u0.x, a1 = *(__nv_bfloat162*)&u0.y;
        __nv_bfloat162 a2 = *(__nv_bfloat162*)&u0.z, a3 = *(__nv_bfloat162*)&u0.w;
        __nv_bfloat162 b0 = *(__nv_bfloat162*)&u1.x, b1 = *(__nv_bfloat162*)&u1.y;
        __nv_bfloat162 b2 = *(__nv_bfloat162*)&u1.z, b3 = *(__nv_bfloat162*)&u1.w;
        acc0 += __bfloat162float(a0.x) * sv0.x + __bfloat162float(a0.y) * sv0.y
              + __bfloat162float(a1.x) * sv0.z + __bfloat162float(a1.y) * sv0.w
              + __bfloat162float(a2.x) * sv1.x + __bfloat162float(a2.y) * sv1.y
              + __bfloat162float(a3.x) * sv1.z + __bfloat162float(a3.y) * sv1.w;
        acc1 += __bfloat162float(b0.x) * sv0.x + __bfloat162float(b0.y) * sv0.y
              + __bfloat162float(b1.x) * sv0.z + __bfloat162float(b1.y) * sv0.w
              + __bfloat162float(b2.x) * sv1.x + __bfloat162float(b2.y) * sv1.y
              + __bfloat162float(b3.x) * sv1.z + __bfloat162float(b3.y) * sv1.w;
    }
    #pragma unroll
    for (int o = 16; o > 0; o >>= 1) {
        acc0 += __shfl_down_sync(0xffffffffu, acc0, o);
        acc1 += __shfl_down_sync(0xffffffffu, acc1, o);
    }
    if (lane == 0) {
        L[row0] = acc0;
        L[row0 + 1] = acc1;
        wmax[wid] = fmaxf(acc0, acc1);
    }
    __syncthreads();
    if (threadIdx.x == 0) {
        float m = wmax[0];
        #pragma unroll
        for (int i = 1; i < 8; i++) m = fmaxf(m, wmax[i]);
        atomicMaxF(&g_max[mat], m);
    }
}

// ---------------- Z = sum exp(L - m) ----------------
__global__ void zsum_kernel() {
    __shared__ float wsum[32];
    int mat = blockIdx.y;
    float m = g_max[mat];
    int i = blockIdx.x * 1024 + threadIdx.x;
    float e = expf(g_logits[mat * AR + i] - m);
    #pragma unroll
    for (int o = 16; o > 0; o >>= 1) e += __shfl_down_sync(0xffffffffu, e, o);
    int wid = threadIdx.x >> 5, lane = threadIdx.x & 31;
    if (lane == 0) wsum[wid] = e;
    __syncthreads();
    if (wid == 0) {
        float v = wsum[lane];
        #pragma unroll
        for (int o = 16; o > 0; o >>= 1) v += __shfl_down_sync(0xffffffffu, v, o);
        if (lane == 0) atomicAdd(&g_z[mat], v);
    }
}

// ---------------- att = seq.T @ softmax(L) ----------------
__global__ void att_kernel(const float* __restrict__ seq1, const float* __restrict__ seq2,
                           float* __restrict__ out) {
    __shared__ float ws[512];
    int mat = blockIdx.z;
    const float* Sq = mat ? seq2 : seq1;
    const float* L = g_logits + mat * AR;
    int c = blockIdx.x * 256 + threadIdx.x;
    int r0 = blockIdx.y * 512;

    float m = g_max[mat];
    float invz = 1.0f / g_z[mat];
    for (int i = threadIdx.x; i < 512; i += 256)
        ws[i] = expf(L[r0 + i] - m) * invz;
    __syncthreads();

    float acc0 = 0.0f, acc1 = 0.0f;
    #pragma unroll 4
    for (int i = 0; i < 512; i += 2) {
        acc0 += Sq[(size_t)(r0 + i) * ED + c] * ws[i];
        acc1 += Sq[(size_t)(r0 + i + 1) * ED + c] * ws[i + 1];
    }
    atomicAdd(&out[mat * ED + c], acc0 + acc1);
}

// ---------------- launch ----------------
extern "C" void kernel_launch(void* const* d_in, const int* in_sizes, int n_in,
                              void* d_out, int out_size) {
    const float* seq1 = (const float*)d_in[0];
    const float* seq2 = (const float*)d_in[1];
    const float* ctx  = (const float*)d_in[2];
    const float* Wc1  = (const float*)d_in[3];
    const float* Wc2  = (const float*)d_in[4];
    const float* W1   = (const float*)d_in[5];
    const float* b1   = (const float*)d_in[6];
    const float* W2   = (const float*)d_in[7];
    const float* b2   = (const float*)d_in[8];
    float* out = (float*)d_out;

    __nv_bfloat16 *a1, *a2, *wb1, *wb2, *p1, *p2;
    float *bias1, *bias2, *s1, *s2;
    cudaGetSymbolAddress((void**)&a1, g_a1);
    cudaGetSymbolAddress((void**)&a2, g_a2);
    cudaGetSymbolAddress((void**)&wb1, g_wb1);
    cudaGetSymbolAddress((void**)&wb2, g_wb2);
    cudaGetSymbolAddress((void**)&p1, g_p1);
    cudaGetSymbolAddress((void**)&p2, g_p2);
    cudaGetSymbolAddress((void**)&bias1, g_bias1);
    cudaGetSymbolAddress((void**)&bias2, g_bias2);
    cudaGetSymbolAddress((void**)&s1, g_s1);
    cudaGetSymbolAddress((void**)&s2, g_s2);

    size_t smem = 2 * STAGE_BYTES + 128;
    cudaFuncSetAttribute(gemm_mma_kernel, cudaFuncAttributeMaxDynamicSharedMemorySize, (int)smem);

    zeroctx_kernel<<<256, 256>>>(ctx, Wc1, Wc2, b1, b2, out);
    conv_all_kernel<<<(TOT_F16 + 255) / 256, 256>>>(seq1, seq2, W1, W2);

    dim3 ggrid(MD / 128, AR / 128, 2);   // 1024 CTAs
    gemm_mma_kernel<<<ggrid, 256, smem>>>(a1, wb1, bias1, p1, s1,
                                          a2, wb2, bias2, p2, s2);

    logits_kernel<<<1024, 256>>>();
    zsum_kernel<<<dim3(8, 2), 1024>>>();
    att_kernel<<<dim3(ED / 256, AR / 512, 2), 256>>>(seq1, seq2, out);
}